// round 11
// baseline (speedup 1.0000x reference)
#include <cuda_runtime.h>
#include <cuda_bf16.h>
#include <cstdint>

#define BATCH 4
#define SEQ   4096
#define CDIM  512
#define DDIM  64
#define MROWS (BATCH*SEQ)
#define NKB   32              // key blocks of 128 in skernel

// device scratch (no allocation allowed)
__device__ __nv_bfloat16 g_xb  [(size_t)MROWS * CDIM];         // bf16 x
__device__ __nv_bfloat16 g_wfgT[128 * CDIM];                   // [Wf;Wg]^T [n][k]
__device__ __nv_bfloat16 g_whT [CDIM * CDIM];                  // Wh^T
__device__ __nv_bfloat16 g_fb  [MROWS * DDIM];                 // f  [m][64]
__device__ __nv_bfloat16 g_gb  [MROWS * DDIM];                 // g  [m][64]
__device__ __nv_bfloat16 g_hTb [(size_t)BATCH * CDIM * SEQ];   // h^T [b][c][n]
__device__ __nv_bfloat16 g_pb  [(size_t)BATCH * SEQ * SEQ];    // P = exp(S) 128 MB
__device__ float         g_lpart[NKB * MROWS];                 // partial row sums
__device__ float         g_l[MROWS];                           // row sums

typedef unsigned int u32;

__device__ __forceinline__ void cp16(void* dst, const void* src) {
    u32 s = (u32)__cvta_generic_to_shared(dst);
    asm volatile("cp.async.cg.shared.global [%0], [%1], 16;\n" :: "r"(s), "l"(src));
}
__device__ __forceinline__ void cp_commit() {
    asm volatile("cp.async.commit_group;\n");
}

__device__ __forceinline__ void mma16816(float* c, const u32* a, u32 b0, u32 b1) {
    asm volatile(
        "mma.sync.aligned.m16n8k16.row.col.f32.bf16.bf16.f32 "
        "{%0,%1,%2,%3}, {%4,%5,%6,%7}, {%8,%9}, {%0,%1,%2,%3};"
        : "+f"(c[0]), "+f"(c[1]), "+f"(c[2]), "+f"(c[3])
        : "r"(a[0]), "r"(a[1]), "r"(a[2]), "r"(a[3]), "r"(b0), "r"(b1));
}

// ---------------------------------------------------------------------------
// Cast kernels
// ---------------------------------------------------------------------------
__global__ void __launch_bounds__(256)
cast_x(const float* __restrict__ x, __nv_bfloat16* __restrict__ xb)
{
    const size_t i = (size_t)blockIdx.x * 256 + threadIdx.x;
    float4 v = ((const float4*)x)[i];
    __nv_bfloat162 a = __floats2bfloat162_rn(v.x, v.y);
    __nv_bfloat162 b = __floats2bfloat162_rn(v.z, v.w);
    *(__nv_bfloat162*)&xb[4 * i]     = a;
    *(__nv_bfloat162*)&xb[4 * i + 2] = b;
}

__global__ void __launch_bounds__(256)
cast_w3(const float* __restrict__ Wf, const float* __restrict__ Wg,
        const float* __restrict__ Wh)
{
    const int i = blockIdx.x * 256 + threadIdx.x;
    if (i < 65536) {                       // [Wf;Wg]^T : n 0..127
        int n = i >> 9, k = i & 511;
        float v = (n < 64) ? Wf[k * DDIM + n] : Wg[k * DDIM + (n - 64)];
        g_wfgT[i] = __float2bfloat16(v);
    } else {                               // Wh^T
        int j = i - 65536;
        int n = j >> 9, k = j & 511;
        g_whT[j] = __float2bfloat16(Wh[k * CDIM + n]);
    }
}

// ---------------------------------------------------------------------------
// Generic bf16 GEMM mainloop: BM=128, BN=NTILES*8, BK=64, 256 thr, 2-deep.
// ---------------------------------------------------------------------------
#define PSTR 72

extern __shared__ __align__(16) unsigned char psm[];

template <int NTILES>
__device__ __forceinline__ void load_chunk(
    const __nv_bfloat16* A, const __nv_bfloat16* BT,
    size_t strA, size_t strB, int m0, int n0, int c, int buf, int t)
{
    constexpr int A_T = 128 * PSTR * 2;
    constexpr int BUF = A_T + NTILES * 8 * PSTR * 2;
    __nv_bfloat16* sA = (__nv_bfloat16*)(psm + buf * BUF);
    __nv_bfloat16* sB = (__nv_bfloat16*)(psm + buf * BUF + A_T);
    #pragma unroll
    for (int r = 0; r < 4; r++) {
        int idx = t + 256 * r;
        int row = idx >> 3, ck = idx & 7;
        cp16(&sA[row * PSTR + ck * 8],
             A + (size_t)(m0 + row) * strA + c * 64 + ck * 8);
    }
    #pragma unroll
    for (int r = 0; r < NTILES / 4; r++) {
        int idx = t + 256 * r;
        int row = idx >> 3, ck = idx & 7;
        cp16(&sB[row * PSTR + ck * 8],
             BT + (size_t)(n0 + row) * strB + c * 64 + ck * 8);
    }
    cp_commit();
}

template <int NCHUNK, int NTILES>
__device__ __forceinline__ void gemm_mainloop(
    const __nv_bfloat16* A, const __nv_bfloat16* BT,
    size_t strA, size_t strB,
    int m0, int n0, int t, int w, int gid, int tig, float (*o)[4])
{
    constexpr int A_T = 128 * PSTR * 2;
    constexpr int BUF = A_T + NTILES * 8 * PSTR * 2;

    #pragma unroll
    for (int nt = 0; nt < NTILES; nt++)
        #pragma unroll
        for (int j = 0; j < 4; j++) o[nt][j] = 0.f;

    load_chunk<NTILES>(A, BT, strA, strB, m0, n0, 0, 0, t);
    load_chunk<NTILES>(A, BT, strA, strB, m0, n0, 1, 1, t);

    for (int c = 0; c < NCHUNK; ++c) {
        if (c + 2 < NCHUNK) asm volatile("cp.async.wait_group 1;\n");
        else                asm volatile("cp.async.wait_group 0;\n");
        __syncthreads();
        const int buf = c & 1;
        const __nv_bfloat16* sA = (const __nv_bfloat16*)(psm + buf * BUF);
        const __nv_bfloat16* sB = (const __nv_bfloat16*)(psm + buf * BUF + A_T);

        u32 fa[4][4];
        const __nv_bfloat16* frow = &sA[(w * 16 + gid) * PSTR];
        #pragma unroll
        for (int ks = 0; ks < 4; ks++) {
            fa[ks][0] = *(const u32*)&frow[ks * 16 + 2 * tig];
            fa[ks][1] = *(const u32*)&frow[8 * PSTR + ks * 16 + 2 * tig];
            fa[ks][2] = *(const u32*)&frow[ks * 16 + 2 * tig + 8];
            fa[ks][3] = *(const u32*)&frow[8 * PSTR + ks * 16 + 2 * tig + 8];
        }
        #pragma unroll
        for (int nt = 0; nt < NTILES; nt++) {
            const __nv_bfloat16* brow = &sB[(nt * 8 + gid) * PSTR + 2 * tig];
            #pragma unroll
            for (int ks = 0; ks < 4; ks++) {
                u32 b0 = *(const u32*)&brow[ks * 16];
                u32 b1 = *(const u32*)&brow[ks * 16 + 8];
                mma16816(o[nt], fa[ks], b0, b1);
            }
        }
        __syncthreads();
        if (c + 2 < NCHUNK) load_chunk<NTILES>(A, BT, strA, strB, m0, n0, c + 2, buf, t);
        else                cp_commit();
    }
}

#define SMEM_N8   ((128 * PSTR * 2 + 64 * PSTR * 2) * 2)    // 55296
#define SMEM_N16  ((128 * PSTR * 2 + 128 * PSTR * 2) * 2)   // 73728

// ---------------------------------------------------------------------------
// proj_fg: f and g in one BN=128 GEMM against [Wf;Wg]^T
// ---------------------------------------------------------------------------
__global__ void __launch_bounds__(256)
proj_fg(const __nv_bfloat16* __restrict__ A,
        const float* __restrict__ bf, const float* __restrict__ bg)
{
    const int m0 = blockIdx.x * 128;
    const int t = threadIdx.x, w = t >> 5, lane = t & 31;
    const int gid = lane >> 2, tig = lane & 3;

    float o[16][4];
    gemm_mainloop<8, 16>(A, g_wfgT, CDIM, CDIM, m0, 0, t, w, gid, tig, o);

    const int r0 = m0 + w * 16 + gid;
    #pragma unroll
    for (int nt = 0; nt < 16; nt++) {
        const int cc = nt * 8 + 2 * tig;           // 0..127
        __nv_bfloat16* dst0;
        __nv_bfloat16* dst1;
        float b0, b1;
        if (nt < 8) {
            b0 = bf[cc]; b1 = bf[cc + 1];
            dst0 = &g_fb[(size_t)r0 * DDIM + cc];
            dst1 = &g_fb[(size_t)(r0 + 8) * DDIM + cc];
        } else {
            b0 = bg[cc - 64]; b1 = bg[cc - 63];
            dst0 = &g_gb[(size_t)r0 * DDIM + cc - 64];
            dst1 = &g_gb[(size_t)(r0 + 8) * DDIM + cc - 64];
        }
        __nv_bfloat162 v0 = __floats2bfloat162_rn(o[nt][0] + b0, o[nt][1] + b1);
        __nv_bfloat162 v1 = __floats2bfloat162_rn(o[nt][2] + b0, o[nt][3] + b1);
        *(__nv_bfloat162*)dst0 = v0;
        *(__nv_bfloat162*)dst1 = v1;
    }
}

// ---------------------------------------------------------------------------
// proj_big: h projection, BN=64, transposed bf16 store
// ---------------------------------------------------------------------------
#define TSTR 136
__global__ void __launch_bounds__(256)
proj_big(const __nv_bfloat16* __restrict__ A, const float* __restrict__ bias)
{
    const int m0 = blockIdx.x * 128;
    const int n0 = blockIdx.y * 64;
    const int t = threadIdx.x, w = t >> 5, lane = t & 31;
    const int gid = lane >> 2, tig = lane & 3;

    float o[8][4];
    gemm_mainloop<8, 8>(A, g_whT, CDIM, CDIM, m0, n0, t, w, gid, tig, o);

    __nv_bfloat16* st = (__nv_bfloat16*)psm;
    __syncthreads();
    const int m = w * 16 + gid;
    #pragma unroll
    for (int nt = 0; nt < 8; nt++) {
        const int cc = nt * 8 + 2 * tig;
        const float b0 = bias[n0 + cc], b1 = bias[n0 + cc + 1];
        st[cc * TSTR + m]           = __float2bfloat16(o[nt][0] + b0);
        st[(cc + 1) * TSTR + m]     = __float2bfloat16(o[nt][1] + b1);
        st[cc * TSTR + m + 8]       = __float2bfloat16(o[nt][2] + b0);
        st[(cc + 1) * TSTR + m + 8] = __float2bfloat16(o[nt][3] + b1);
    }
    __syncthreads();

    const int b  = m0 >> 12;
    const int nb = m0 & 4095;
    #pragma unroll
    for (int r = 0; r < 4; r++) {
        int idx = t + 256 * r;
        int row = idx >> 4, seg = idx & 15;
        float4 v = *(const float4*)&st[row * TSTR + seg * 8];
        *(float4*)&g_hTb[((size_t)b * CDIM + n0 + row) * SEQ + nb + seg * 8] = v;
    }
}

// ---------------------------------------------------------------------------
// skernel: P[q][k] = exp(f_q . g_k) for one batch; coalesced stores via
// smem transpose (reuses the f/g buffer), plus partial row sums.
// ---------------------------------------------------------------------------
#define PTS 136        // staging stride (bf16): 272 B rows, 16B-aligned

__global__ void __launch_bounds__(256)
skernel(int b)
{
    __shared__ __nv_bfloat16 sbuf[2 * 128 * PSTR];   // 36864 B; reused for P tile

    __nv_bfloat16* sf = sbuf;
    __nv_bfloat16* sg = sbuf + 128 * PSTR;

    const int qb = blockIdx.x, kb = blockIdx.y;
    const int q0 = qb * 128, k0 = kb * 128;
    const int t = threadIdx.x, w = t >> 5, lane = t & 31;
    const int gid = lane >> 2, tig = lane & 3;

    const __nv_bfloat16* fptr = g_fb + (size_t)(b * SEQ + q0) * DDIM;
    const __nv_bfloat16* gptr = g_gb + (size_t)(b * SEQ + k0) * DDIM;
    #pragma unroll
    for (int r = 0; r < 4; r++) {
        int idx = t + 256 * r;
        int row = idx >> 3, ck = idx & 7;
        cp16(&sf[row * PSTR + ck * 8], fptr + (size_t)row * DDIM + ck * 8);
    }
    #pragma unroll
    for (int r = 0; r < 4; r++) {
        int idx = t + 256 * r;
        int row = idx >> 3, ck = idx & 7;
        cp16(&sg[row * PSTR + ck * 8], gptr + (size_t)row * DDIM + ck * 8);
    }
    cp_commit();
    asm volatile("cp.async.wait_group 0;\n");
    __syncthreads();

    u32 fa[4][4];
    {
        const __nv_bfloat16* frow = &sf[(w * 16 + gid) * PSTR];
        #pragma unroll
        for (int ks = 0; ks < 4; ks++) {
            fa[ks][0] = *(const u32*)&frow[ks * 16 + 2 * tig];
            fa[ks][1] = *(const u32*)&frow[8 * PSTR + ks * 16 + 2 * tig];
            fa[ks][2] = *(const u32*)&frow[ks * 16 + 2 * tig + 8];
            fa[ks][3] = *(const u32*)&frow[8 * PSTR + ks * 16 + 2 * tig + 8];
        }
    }

    float s[16][4];
    #pragma unroll
    for (int nt = 0; nt < 16; nt++)
        #pragma unroll
        for (int j = 0; j < 4; j++) s[nt][j] = 0.f;

    #pragma unroll
    for (int nt = 0; nt < 16; nt++) {
        const __nv_bfloat16* brow = &sg[(nt * 8 + gid) * PSTR + 2 * tig];
        #pragma unroll
        for (int ks = 0; ks < 4; ks++) {
            u32 b0 = *(const u32*)&brow[ks * 16];
            u32 b1 = *(const u32*)&brow[ks * 16 + 8];
            mma16816(s[nt], fa[ks], b0, b1);
        }
    }
    __syncthreads();   // all reads of sf/sg done; sbuf is now the P staging tile

    __nv_bfloat16* sp = sbuf;
    const int rl0 = w * 16 + gid;          // local row 0..127
    const int rl1 = rl0 + 8;
    float sl0 = 0.f, sl1 = 0.f;
    #pragma unroll
    for (int nt = 0; nt < 16; nt++) {
        float p0 = __expf(s[nt][0]);
        float p1 = __expf(s[nt][1]);
        float p2 = __expf(s[nt][2]);
        float p3 = __expf(s[nt][3]);
        sl0 += p0 + p1;
        sl1 += p2 + p3;
        const int key = nt * 8 + 2 * tig;
        __nv_bfloat162 lo = __floats2bfloat162_rn(p0, p1);
        __nv_bfloat162 hi = __floats2bfloat162_rn(p2, p3);
        *(__nv_bfloat162*)&sp[rl0 * PTS + key] = lo;
        *(__nv_bfloat162*)&sp[rl1 * PTS + key] = hi;
    }
    sl0 += __shfl_xor_sync(0xffffffffu, sl0, 1);
    sl0 += __shfl_xor_sync(0xffffffffu, sl0, 2);
    sl1 += __shfl_xor_sync(0xffffffffu, sl1, 1);
    sl1 += __shfl_xor_sync(0xffffffffu, sl1, 2);
    if (tig == 0) {
        g_lpart[kb * MROWS + b * SEQ + q0 + rl0] = sl0;
        g_lpart[kb * MROWS + b * SEQ + q0 + rl1] = sl1;
    }
    __syncthreads();

    // coalesced 16B stores: 128 rows x 16 float4
    __nv_bfloat16* P = g_pb + (size_t)b * SEQ * SEQ;
    #pragma unroll
    for (int r = 0; r < 8; r++) {
        int idx = t + 256 * r;
        int row = idx >> 4, seg = idx & 15;
        float4 v = *(const float4*)&sp[row * PTS + seg * 8];
        *(float4*)&P[(size_t)(q0 + row) * SEQ + k0 + seg * 8] = v;
    }
}

__global__ void __launch_bounds__(256)
reduce_l(int b)
{
    const int m = b * SEQ + blockIdx.x * 256 + threadIdx.x;
    float s = 0.f;
    #pragma unroll
    for (int kb = 0; kb < NKB; kb++) s += g_lpart[kb * MROWS + m];
    g_l[m] = s;
}

// ---------------------------------------------------------------------------
// pvkernel: out = x + (gamma/l[row]) * (P . h^T). BN=128, one batch.
// ---------------------------------------------------------------------------
__global__ void __launch_bounds__(256)
pvkernel(int b, const float* __restrict__ x, const float* __restrict__ gamma_p,
         float* __restrict__ out)
{
    const int n0 = blockIdx.x * 128;    // channel block (x-major for P L2 reuse)
    const int q0 = blockIdx.y * 128;    // row block within batch
    const int t = threadIdx.x, w = t >> 5, lane = t & 31;
    const int gid = lane >> 2, tig = lane & 3;

    const __nv_bfloat16* Pq = g_pb + ((size_t)b * SEQ + q0) * SEQ;
    const __nv_bfloat16* BT = g_hTb + (size_t)b * CDIM * SEQ;

    float o[16][4];
    gemm_mainloop<SEQ / 64, 16>(Pq, BT, SEQ, SEQ, 0, n0, t, w, gid, tig, o);

    const float gamma = *gamma_p;
    const int r0 = b * SEQ + q0 + w * 16 + gid;
    const int r1 = r0 + 8;
    const float sc0 = gamma / g_l[r0];
    const float sc1 = gamma / g_l[r1];
    #pragma unroll
    for (int nt = 0; nt < 16; nt++) {
        const int cc = n0 + nt * 8 + 2 * tig;
        float2 x0 = *(const float2*)&x[(size_t)r0 * CDIM + cc];
        float2 x1 = *(const float2*)&x[(size_t)r1 * CDIM + cc];
        float2 o0, o1;
        o0.x = fmaf(o[nt][0], sc0, x0.x);
        o0.y = fmaf(o[nt][1], sc0, x0.y);
        o1.x = fmaf(o[nt][2], sc1, x1.x);
        o1.y = fmaf(o[nt][3], sc1, x1.y);
        *(float2*)&out[(size_t)r0 * CDIM + cc] = o0;
        *(float2*)&out[(size_t)r1 * CDIM + cc] = o1;
    }
}

// ---------------------------------------------------------------------------
extern "C" void kernel_launch(void* const* d_in, const int* in_sizes, int n_in,
                              void* d_out, int out_size)
{
    const float* x     = (const float*)d_in[0];
    const float* Wf    = (const float*)d_in[1];
    const float* bf    = (const float*)d_in[2];
    const float* Wg    = (const float*)d_in[3];
    const float* bg    = (const float*)d_in[4];
    const float* Wh    = (const float*)d_in[5];
    const float* bh    = (const float*)d_in[6];
    const float* gamma = (const float*)d_in[7];
    float* out = (float*)d_out;

    __nv_bfloat16* xb;
    cudaGetSymbolAddress((void**)&xb, g_xb);

    static cudaStream_t s1 = nullptr;
    static cudaEvent_t  e0 = nullptr;
    static cudaEvent_t  esk[BATCH] = {nullptr, nullptr, nullptr, nullptr};
    if (!s1) {
        cudaStreamCreateWithFlags(&s1, cudaStreamNonBlocking);
        cudaEventCreateWithFlags(&e0, cudaEventDisableTiming);
        for (int b = 0; b < BATCH; b++)
            cudaEventCreateWithFlags(&esk[b], cudaEventDisableTiming);
        cudaFuncSetAttribute(proj_fg,
                             cudaFuncAttributeMaxDynamicSharedMemorySize, SMEM_N16);
        cudaFuncSetAttribute(proj_big,
                             cudaFuncAttributeMaxDynamicSharedMemorySize, SMEM_N8);
        cudaFuncSetAttribute(pvkernel,
                             cudaFuncAttributeMaxDynamicSharedMemorySize, SMEM_N16);
    }

    // default stream: casts, then fork
    cast_x <<<MROWS * CDIM / 4 / 256, 256>>>(x, xb);
    cast_w3<<<(65536 + CDIM * CDIM) / 256, 256>>>(Wf, Wg, Wh);
    cudaEventRecord(e0, 0);

    // side stream: f+g projection -> per-batch S/P/exp + l reduction
    cudaStreamWaitEvent(s1, e0, 0);
    proj_fg<<<dim3(MROWS / 128), 256, SMEM_N16, s1>>>(xb, bf, bg);
    for (int b = 0; b < BATCH; b++) {
        skernel <<<dim3(SEQ / 128, SEQ / 128), 256, 0, s1>>>(b);
        reduce_l<<<SEQ / 256, 256, 0, s1>>>(b);
        cudaEventRecord(esk[b], s1);
    }

    // default stream: h projection overlaps the side stream
    proj_big<<<dim3(MROWS / 128, CDIM / 64), 256, SMEM_N8>>>(xb, bh);

    // per-batch PV as soon as its P slab + l are ready (and h, by stream order)
    for (int b = 0; b < BATCH; b++) {
        cudaStreamWaitEvent(0, esk[b], 0);
        pvkernel<<<dim3(CDIM / 128, SEQ / 128), 256, SMEM_N16>>>(b, x, gamma, out);
    }
}

// round 16
// speedup vs baseline: 1.0707x; 1.0707x over previous
#include <cuda_runtime.h>
#include <cuda_bf16.h>
#include <cstdint>

#define BATCH 4
#define SEQ   4096
#define CDIM  512
#define DDIM  64
#define MROWS (BATCH*SEQ)
#define NKB   32              // key blocks of 128 in skernel

// device scratch (no allocation allowed)
__device__ __nv_bfloat16 g_xb  [(size_t)MROWS * CDIM];         // bf16 x (k-permuted)
__device__ __nv_bfloat16 g_wfgT[128 * CDIM];                   // [Wf;Wg]^T (k-permuted)
__device__ __nv_bfloat16 g_whT [CDIM * CDIM];                  // Wh^T (k-permuted)
__device__ __nv_bfloat16 g_fb  [MROWS * DDIM];                 // f (d-permuted)
__device__ __nv_bfloat16 g_gb  [MROWS * DDIM];                 // g (d-permuted)
__device__ __nv_bfloat16 g_hTb [(size_t)BATCH * CDIM * SEQ];   // h^T (key-permuted)
__device__ __nv_bfloat16 g_pb  [(size_t)BATCH * SEQ * SEQ];    // P (key-permuted) 128 MB
__device__ float         g_lpart[NKB * MROWS];                 // partial row sums
__device__ float         g_l[MROWS];                           // row sums

typedef unsigned int u32;

// k-permutation within each 64-element group: u32 idx [ks|half|tig] -> [tig|half|ks]
__device__ __forceinline__ int kperm(int e) {
    int u = (e >> 1) & 31;
    int ks = u >> 3, hf = (u >> 2) & 1, tg = u & 3;
    return (e & ~63) | (tg << 4) | (hf << 3) | (ks << 1) | (e & 1);
}

__device__ __forceinline__ void cp16(void* dst, const void* src) {
    u32 s = (u32)__cvta_generic_to_shared(dst);
    asm volatile("cp.async.cg.shared.global [%0], [%1], 16;\n" :: "r"(s), "l"(src));
}
__device__ __forceinline__ void cp_commit() {
    asm volatile("cp.async.commit_group;\n");
}

__device__ __forceinline__ void mma16816(float* c, const u32* a, u32 b0, u32 b1) {
    asm volatile(
        "mma.sync.aligned.m16n8k16.row.col.f32.bf16.bf16.f32 "
        "{%0,%1,%2,%3}, {%4,%5,%6,%7}, {%8,%9}, {%0,%1,%2,%3};"
        : "+f"(c[0]), "+f"(c[1]), "+f"(c[2]), "+f"(c[3])
        : "r"(a[0]), "r"(a[1]), "r"(a[2]), "r"(a[3]), "r"(b0), "r"(b1));
}

// ---------------------------------------------------------------------------
// Cast kernels (write k-permuted layouts)
// ---------------------------------------------------------------------------
__global__ void __launch_bounds__(256)
cast_x(const float* __restrict__ x, __nv_bfloat16* __restrict__ xb)
{
    const size_t i = (size_t)blockIdx.x * 256 + threadIdx.x;
    float4 v = ((const float4*)x)[i];
    __nv_bfloat162 a = __floats2bfloat162_rn(v.x, v.y);
    __nv_bfloat162 b = __floats2bfloat162_rn(v.z, v.w);
    const size_t e0 = 4 * i;
    const size_t grp = e0 & ~(size_t)63;
    const int    el  = (int)(e0 & 63);
    *(__nv_bfloat162*)&xb[grp + kperm(el)]     = a;
    *(__nv_bfloat162*)&xb[grp + kperm(el + 2)] = b;
}

__global__ void __launch_bounds__(256)
cast_w3(const float* __restrict__ Wf, const float* __restrict__ Wg,
        const float* __restrict__ Wh)
{
    const int i = blockIdx.x * 256 + threadIdx.x;
    if (i < 65536) {                       // [Wf;Wg]^T : n 0..127
        int n = i >> 9, k = i & 511;
        float v = (n < 64) ? Wf[k * DDIM + n] : Wg[k * DDIM + (n - 64)];
        g_wfgT[n * CDIM + kperm(k)] = __float2bfloat16(v);
    } else {                               // Wh^T
        int j = i - 65536;
        int n = j >> 9, k = j & 511;
        g_whT[n * CDIM + kperm(k)] = __float2bfloat16(Wh[k * CDIM + n]);
    }
}

// ---------------------------------------------------------------------------
// Vectorized bf16 GEMM mainloop: BM=128, BN=NTILES*8, BK=64, 256 thr, 2-deep.
// Operands are k-permuted -> fragment loads are LDS.128.
// ---------------------------------------------------------------------------
#define PSTR 72

extern __shared__ __align__(16) unsigned char psm[];

template <int NTILES>
__device__ __forceinline__ void load_chunk(
    const __nv_bfloat16* A, const __nv_bfloat16* BT,
    size_t strA, size_t strB, int m0, int n0, int c, int buf, int t)
{
    constexpr int A_T = 128 * PSTR * 2;
    constexpr int BUF = A_T + NTILES * 8 * PSTR * 2;
    __nv_bfloat16* sA = (__nv_bfloat16*)(psm + buf * BUF);
    __nv_bfloat16* sB = (__nv_bfloat16*)(psm + buf * BUF + A_T);
    #pragma unroll
    for (int r = 0; r < 4; r++) {
        int idx = t + 256 * r;
        int row = idx >> 3, ck = idx & 7;
        cp16(&sA[row * PSTR + ck * 8],
             A + (size_t)(m0 + row) * strA + c * 64 + ck * 8);
    }
    #pragma unroll
    for (int r = 0; r < NTILES / 4; r++) {
        int idx = t + 256 * r;
        int row = idx >> 3, ck = idx & 7;
        cp16(&sB[row * PSTR + ck * 8],
             BT + (size_t)(n0 + row) * strB + c * 64 + ck * 8);
    }
    cp_commit();
}

template <int NCHUNK, int NTILES>
__device__ __forceinline__ void gemm_mainloop(
    const __nv_bfloat16* A, const __nv_bfloat16* BT,
    size_t strA, size_t strB,
    int m0, int n0, int t, int w, int gid, int tig, float (*o)[4])
{
    constexpr int A_T = 128 * PSTR * 2;
    constexpr int BUF = A_T + NTILES * 8 * PSTR * 2;

    #pragma unroll
    for (int nt = 0; nt < NTILES; nt++)
        #pragma unroll
        for (int j = 0; j < 4; j++) o[nt][j] = 0.f;

    load_chunk<NTILES>(A, BT, strA, strB, m0, n0, 0, 0, t);
    load_chunk<NTILES>(A, BT, strA, strB, m0, n0, 1, 1, t);

    for (int c = 0; c < NCHUNK; ++c) {
        if (c + 2 < NCHUNK) asm volatile("cp.async.wait_group 1;\n");
        else                asm volatile("cp.async.wait_group 0;\n");
        __syncthreads();
        const int buf = c & 1;
        const __nv_bfloat16* sA = (const __nv_bfloat16*)(psm + buf * BUF);
        const __nv_bfloat16* sB = (const __nv_bfloat16*)(psm + buf * BUF + A_T);

        u32 fa[4][4];
        {
            const __nv_bfloat16* frow = &sA[(w * 16 + gid) * PSTR];
            float4 a0 = *(const float4*)&frow[tig * 16];
            float4 a1 = *(const float4*)&frow[tig * 16 + 8];
            float4 a2 = *(const float4*)&frow[8 * PSTR + tig * 16];
            float4 a3 = *(const float4*)&frow[8 * PSTR + tig * 16 + 8];
            const u32* p0 = (const u32*)&a0;
            const u32* p1 = (const u32*)&a1;
            const u32* p2 = (const u32*)&a2;
            const u32* p3 = (const u32*)&a3;
            #pragma unroll
            for (int ks = 0; ks < 4; ks++) {
                fa[ks][0] = p0[ks]; fa[ks][1] = p2[ks];
                fa[ks][2] = p1[ks]; fa[ks][3] = p3[ks];
            }
        }
        #pragma unroll
        for (int nt = 0; nt < NTILES; nt++) {
            const __nv_bfloat16* brow = &sB[(nt * 8 + gid) * PSTR];
            float4 bl = *(const float4*)&brow[tig * 16];
            float4 bh = *(const float4*)&brow[tig * 16 + 8];
            const u32* ql = (const u32*)&bl;
            const u32* qh = (const u32*)&bh;
            #pragma unroll
            for (int ks = 0; ks < 4; ks++)
                mma16816(o[nt], fa[ks], ql[ks], qh[ks]);
        }
        __syncthreads();
        if (c + 2 < NCHUNK) load_chunk<NTILES>(A, BT, strA, strB, m0, n0, c + 2, buf, t);
        else                cp_commit();
    }
}

#define SMEM_N8   ((128 * PSTR * 2 + 64 * PSTR * 2) * 2)    // 55296
#define SMEM_N16  ((128 * PSTR * 2 + 128 * PSTR * 2) * 2)   // 73728

// ---------------------------------------------------------------------------
// proj_fg: f and g in one BN=128 GEMM; outputs k-permuted for skernel
// ---------------------------------------------------------------------------
__global__ void __launch_bounds__(256)
proj_fg(const __nv_bfloat16* __restrict__ A,
        const float* __restrict__ bf, const float* __restrict__ bg)
{
    const int m0 = blockIdx.x * 128;
    const int t = threadIdx.x, w = t >> 5, lane = t & 31;
    const int gid = lane >> 2, tig = lane & 3;

    float o[16][4];
    gemm_mainloop<8, 16>(A, g_wfgT, CDIM, CDIM, m0, 0, t, w, gid, tig, o);

    const int r0 = m0 + w * 16 + gid;
    #pragma unroll
    for (int nt = 0; nt < 16; nt++) {
        const int cc = nt * 8 + 2 * tig;           // 0..127 (semantic)
        __nv_bfloat16* dst0;
        __nv_bfloat16* dst1;
        float b0, b1;
        if (nt < 8) {
            b0 = bf[cc]; b1 = bf[cc + 1];
            const int cp = kperm(cc);              // within 0..63
            dst0 = &g_fb[(size_t)r0 * DDIM + cp];
            dst1 = &g_fb[(size_t)(r0 + 8) * DDIM + cp];
        } else {
            b0 = bg[cc - 64]; b1 = bg[cc - 63];
            const int cp = kperm(cc - 64);
            dst0 = &g_gb[(size_t)r0 * DDIM + cp];
            dst1 = &g_gb[(size_t)(r0 + 8) * DDIM + cp];
        }
        __nv_bfloat162 v0 = __floats2bfloat162_rn(o[nt][0] + b0, o[nt][1] + b1);
        __nv_bfloat162 v1 = __floats2bfloat162_rn(o[nt][2] + b0, o[nt][3] + b1);
        *(__nv_bfloat162*)dst0 = v0;
        *(__nv_bfloat162*)dst1 = v1;
    }
}

// ---------------------------------------------------------------------------
// proj_big: h projection, BN=64, transposed store, key-dim permuted for pv
// ---------------------------------------------------------------------------
#define TSTR 136
__global__ void __launch_bounds__(256)
proj_big(const __nv_bfloat16* __restrict__ A, const float* __restrict__ bias)
{
    const int m0 = blockIdx.x * 128;
    const int n0 = blockIdx.y * 64;
    const int t = threadIdx.x, w = t >> 5, lane = t & 31;
    const int gid = lane >> 2, tig = lane & 3;

    float o[8][4];
    gemm_mainloop<8, 8>(A, g_whT, CDIM, CDIM, m0, n0, t, w, gid, tig, o);

    __nv_bfloat16* st = (__nv_bfloat16*)psm;
    __syncthreads();
    const int m  = w * 16 + gid;
    const int mp  = kperm(m);          // key-dim permutation (columns of st)
    const int mp8 = kperm(m + 8);
    #pragma unroll
    for (int nt = 0; nt < 8; nt++) {
        const int cc = nt * 8 + 2 * tig;
        const float b0 = bias[n0 + cc], b1 = bias[n0 + cc + 1];
        st[cc * TSTR + mp]        = __float2bfloat16(o[nt][0] + b0);
        st[(cc + 1) * TSTR + mp]  = __float2bfloat16(o[nt][1] + b1);
        st[cc * TSTR + mp8]       = __float2bfloat16(o[nt][2] + b0);
        st[(cc + 1) * TSTR + mp8] = __float2bfloat16(o[nt][3] + b1);
    }
    __syncthreads();

    const int b  = m0 >> 12;
    const int nb = m0 & 4095;
    #pragma unroll
    for (int r = 0; r < 4; r++) {
        int idx = t + 256 * r;
        int row = idx >> 4, seg = idx & 15;
        float4 v = *(const float4*)&st[row * TSTR + seg * 8];
        *(float4*)&g_hTb[((size_t)b * CDIM + n0 + row) * SEQ + nb + seg * 8] = v;
    }
}

// ---------------------------------------------------------------------------
// skernel: P = exp(f.g) with vectorized frag loads; P staged key-permuted.
// ---------------------------------------------------------------------------
#define PTS 136
__global__ void __launch_bounds__(256)
skernel()
{
    __shared__ __align__(16) __nv_bfloat16 sbuf[2 * 128 * PSTR];  // 36864 B

    __nv_bfloat16* sf = sbuf;
    __nv_bfloat16* sg = sbuf + 128 * PSTR;

    const int qb = blockIdx.x, kb = blockIdx.y, b = blockIdx.z;
    const int q0 = qb * 128, k0 = kb * 128;
    const int t = threadIdx.x, w = t >> 5, lane = t & 31;
    const int gid = lane >> 2, tig = lane & 3;

    const __nv_bfloat16* fptr = g_fb + (size_t)(b * SEQ + q0) * DDIM;
    const __nv_bfloat16* gptr = g_gb + (size_t)(b * SEQ + k0) * DDIM;
    #pragma unroll
    for (int r = 0; r < 4; r++) {
        int idx = t + 256 * r;
        int row = idx >> 3, ck = idx & 7;
        cp16(&sf[row * PSTR + ck * 8], fptr + (size_t)row * DDIM + ck * 8);
    }
    #pragma unroll
    for (int r = 0; r < 4; r++) {
        int idx = t + 256 * r;
        int row = idx >> 3, ck = idx & 7;
        cp16(&sg[row * PSTR + ck * 8], gptr + (size_t)row * DDIM + ck * 8);
    }
    cp_commit();
    asm volatile("cp.async.wait_group 0;\n");
    __syncthreads();

    u32 fa[4][4];
    {
        const __nv_bfloat16* frow = &sf[(w * 16 + gid) * PSTR];
        float4 a0 = *(const float4*)&frow[tig * 16];
        float4 a1 = *(const float4*)&frow[tig * 16 + 8];
        float4 a2 = *(const float4*)&frow[8 * PSTR + tig * 16];
        float4 a3 = *(const float4*)&frow[8 * PSTR + tig * 16 + 8];
        const u32* p0 = (const u32*)&a0;
        const u32* p1 = (const u32*)&a1;
        const u32* p2 = (const u32*)&a2;
        const u32* p3 = (const u32*)&a3;
        #pragma unroll
        for (int ks = 0; ks < 4; ks++) {
            fa[ks][0] = p0[ks]; fa[ks][1] = p2[ks];
            fa[ks][2] = p1[ks]; fa[ks][3] = p3[ks];
        }
    }

    float s[16][4];
    #pragma unroll
    for (int nt = 0; nt < 16; nt++)
        #pragma unroll
        for (int j = 0; j < 4; j++) s[nt][j] = 0.f;

    #pragma unroll
    for (int nt = 0; nt < 16; nt++) {
        const __nv_bfloat16* brow = &sg[(nt * 8 + gid) * PSTR];
        float4 bl = *(const float4*)&brow[tig * 16];
        float4 bh = *(const float4*)&brow[tig * 16 + 8];
        const u32* ql = (const u32*)&bl;
        const u32* qh = (const u32*)&bh;
        #pragma unroll
        for (int ks = 0; ks < 4; ks++)
            mma16816(s[nt], fa[ks], ql[ks], qh[ks]);
    }
    __syncthreads();   // sf/sg reads done; sbuf becomes the P staging tile

    __nv_bfloat16* sp = sbuf;
    const int rl0 = w * 16 + gid;
    const int rl1 = rl0 + 8;
    float sl0 = 0.f, sl1 = 0.f;
    #pragma unroll
    for (int nt = 0; nt < 16; nt++) {
        float p0 = __expf(s[nt][0]);
        float p1 = __expf(s[nt][1]);
        float p2 = __expf(s[nt][2]);
        float p3 = __expf(s[nt][3]);
        sl0 += p0 + p1;
        sl1 += p2 + p3;
        const int key = kperm(nt * 8 + 2 * tig);   // key-permuted for pv A-frags
        __nv_bfloat162 lo = __floats2bfloat162_rn(p0, p1);
        __nv_bfloat162 hi = __floats2bfloat162_rn(p2, p3);
        *(__nv_bfloat162*)&sp[rl0 * PTS + key] = lo;
        *(__nv_bfloat162*)&sp[rl1 * PTS + key] = hi;
    }
    sl0 += __shfl_xor_sync(0xffffffffu, sl0, 1);
    sl0 += __shfl_xor_sync(0xffffffffu, sl0, 2);
    sl1 += __shfl_xor_sync(0xffffffffu, sl1, 1);
    sl1 += __shfl_xor_sync(0xffffffffu, sl1, 2);
    if (tig == 0) {
        g_lpart[kb * MROWS + b * SEQ + q0 + rl0] = sl0;
        g_lpart[kb * MROWS + b * SEQ + q0 + rl1] = sl1;
    }
    __syncthreads();

    __nv_bfloat16* P = g_pb + (size_t)b * SEQ * SEQ;
    #pragma unroll
    for (int r = 0; r < 8; r++) {
        int idx = t + 256 * r;
        int row = idx >> 4, seg = idx & 15;
        float4 v = *(const float4*)&sp[row * PTS + seg * 8];
        *(float4*)&P[(size_t)(q0 + row) * SEQ + k0 + seg * 8] = v;
    }
}

__global__ void __launch_bounds__(256)
reduce_l()
{
    const int m = blockIdx.x * 256 + threadIdx.x;
    float s = 0.f;
    #pragma unroll
    for (int kb = 0; kb < NKB; kb++) s += g_lpart[kb * MROWS + m];
    g_l[m] = s;
}

// ---------------------------------------------------------------------------
// pvkernel: out = x + (gamma/l[row]) * (P . h^T). BN=128, vectorized frags.
// ---------------------------------------------------------------------------
__global__ void __launch_bounds__(256)
pvkernel(const float* __restrict__ x, const float* __restrict__ gamma_p,
         float* __restrict__ out)
{
    const int n0 = blockIdx.x * 128;    // channel block (x-major for P L2 reuse)
    const int m0 = blockIdx.y * 128;    // global row block
    const int b  = m0 >> 12;
    const int t = threadIdx.x, w = t >> 5, lane = t & 31;
    const int gid = lane >> 2, tig = lane & 3;

    const __nv_bfloat16* Pq = g_pb + ((size_t)b * SEQ + (m0 & 4095)) * SEQ;
    const __nv_bfloat16* BT = g_hTb + (size_t)b * CDIM * SEQ;

    float o[16][4];
    gemm_mainloop<SEQ / 64, 16>(Pq, BT, SEQ, SEQ, 0, n0, t, w, gid, tig, o);

    const float gamma = *gamma_p;
    const int r0 = m0 + w * 16 + gid;
    const int r1 = r0 + 8;
    const float sc0 = gamma / g_l[r0];
    const float sc1 = gamma / g_l[r1];
    #pragma unroll
    for (int nt = 0; nt < 16; nt++) {
        const int cc = n0 + nt * 8 + 2 * tig;
        float2 x0 = *(const float2*)&x[(size_t)r0 * CDIM + cc];
        float2 x1 = *(const float2*)&x[(size_t)r1 * CDIM + cc];
        float2 o0, o1;
        o0.x = fmaf(o[nt][0], sc0, x0.x);
        o0.y = fmaf(o[nt][1], sc0, x0.y);
        o1.x = fmaf(o[nt][2], sc1, x1.x);
        o1.y = fmaf(o[nt][3], sc1, x1.y);
        *(float2*)&out[(size_t)r0 * CDIM + cc] = o0;
        *(float2*)&out[(size_t)r1 * CDIM + cc] = o1;
    }
}

// ---------------------------------------------------------------------------
extern "C" void kernel_launch(void* const* d_in, const int* in_sizes, int n_in,
                              void* d_out, int out_size)
{
    const float* x     = (const float*)d_in[0];
    const float* Wf    = (const float*)d_in[1];
    const float* bf    = (const float*)d_in[2];
    const float* Wg    = (const float*)d_in[3];
    const float* bg    = (const float*)d_in[4];
    const float* Wh    = (const float*)d_in[5];
    const float* bh    = (const float*)d_in[6];
    const float* gamma = (const float*)d_in[7];
    float* out = (float*)d_out;

    __nv_bfloat16* xb;
    cudaGetSymbolAddress((void**)&xb, g_xb);

    static cudaStream_t s1 = nullptr;
    static cudaEvent_t  e0 = nullptr, e1 = nullptr;
    if (!s1) {
        cudaStreamCreateWithFlags(&s1, cudaStreamNonBlocking);
        cudaEventCreateWithFlags(&e0, cudaEventDisableTiming);
        cudaEventCreateWithFlags(&e1, cudaEventDisableTiming);
        cudaFuncSetAttribute(proj_fg,
                             cudaFuncAttributeMaxDynamicSharedMemorySize, SMEM_N16);
        cudaFuncSetAttribute(proj_big,
                             cudaFuncAttributeMaxDynamicSharedMemorySize, SMEM_N8);
        cudaFuncSetAttribute(pvkernel,
                             cudaFuncAttributeMaxDynamicSharedMemorySize, SMEM_N16);
    }

    // default stream: casts, then fork
    cast_x <<<MROWS * CDIM / 4 / 256, 256>>>(x, xb);
    cast_w3<<<(65536 + CDIM * CDIM) / 256, 256>>>(Wf, Wg, Wh);
    cudaEventRecord(e0, 0);

    // side stream: f+g projection -> S/P/exp -> l reduction
    cudaStreamWaitEvent(s1, e0, 0);
    proj_fg <<<dim3(MROWS / 128), 256, SMEM_N16, s1>>>(xb, bf, bg);
    skernel <<<dim3(SEQ / 128, SEQ / 128, BATCH), 256, 0, s1>>>();
    reduce_l<<<MROWS / 256, 256, 0, s1>>>();
    cudaEventRecord(e1, s1);

    // default stream: h projection overlaps the side stream
    proj_big<<<dim3(MROWS / 128, CDIM / 64), 256, SMEM_N8>>>(xb, bh);

    // join, then PV
    cudaStreamWaitEvent(0, e1, 0);
    pvkernel<<<dim3(CDIM / 128, MROWS / 128), 256, SMEM_N16>>>(x, gamma, out);
}

// round 17
// speedup vs baseline: 1.1916x; 1.1129x over previous
#include <cuda_runtime.h>
#include <cuda_bf16.h>
#include <cstdint>

#define BATCH 4
#define SEQ   4096
#define CDIM  512
#define DDIM  64
#define MROWS (BATCH*SEQ)
#define NKB   32              // key blocks of 128 in skernel

// device scratch (no allocation allowed)
__device__ __nv_bfloat16 g_xb  [(size_t)MROWS * CDIM];         // bf16 x
__device__ __nv_bfloat16 g_wfgT[128 * CDIM];                   // [Wf;Wg]^T [n][k]
__device__ __nv_bfloat16 g_whT [CDIM * CDIM];                  // Wh^T
__device__ __nv_bfloat16 g_fb  [MROWS * DDIM];                 // f  [m][64]
__device__ __nv_bfloat16 g_gb  [MROWS * DDIM];                 // g  [m][64]
__device__ __nv_bfloat16 g_hTb [(size_t)BATCH * CDIM * SEQ];   // h^T [b][c][n]
__device__ __nv_bfloat16 g_pb  [(size_t)BATCH * SEQ * SEQ];    // P = exp(S) 128 MB
__device__ float         g_lpart[NKB * MROWS];                 // partial row sums
__device__ float         g_l[MROWS];                           // row sums

typedef unsigned int u32;

__device__ __forceinline__ void cp16(void* dst, const void* src) {
    u32 s = (u32)__cvta_generic_to_shared(dst);
    asm volatile("cp.async.cg.shared.global [%0], [%1], 16;\n" :: "r"(s), "l"(src));
}
__device__ __forceinline__ void cp_commit() {
    asm volatile("cp.async.commit_group;\n");
}

__device__ __forceinline__ void mma16816(float* c, const u32* a, u32 b0, u32 b1) {
    asm volatile(
        "mma.sync.aligned.m16n8k16.row.col.f32.bf16.bf16.f32 "
        "{%0,%1,%2,%3}, {%4,%5,%6,%7}, {%8,%9}, {%0,%1,%2,%3};"
        : "+f"(c[0]), "+f"(c[1]), "+f"(c[2]), "+f"(c[3])
        : "r"(a[0]), "r"(a[1]), "r"(a[2]), "r"(a[3]), "r"(b0), "r"(b1));
}

// ---------------------------------------------------------------------------
// Cast kernels
// ---------------------------------------------------------------------------
__global__ void __launch_bounds__(256)
cast_x(const float* __restrict__ x, __nv_bfloat16* __restrict__ xb)
{
    const size_t i = (size_t)blockIdx.x * 256 + threadIdx.x;
    float4 v = ((const float4*)x)[i];
    __nv_bfloat162 a = __floats2bfloat162_rn(v.x, v.y);
    __nv_bfloat162 b = __floats2bfloat162_rn(v.z, v.w);
    *(__nv_bfloat162*)&xb[4 * i]     = a;
    *(__nv_bfloat162*)&xb[4 * i + 2] = b;
}

// weight transpose-casts: [Wf;Wg]^T combined + Wh^T
__global__ void __launch_bounds__(256)
cast_w3(const float* __restrict__ Wf, const float* __restrict__ Wg,
        const float* __restrict__ Wh)
{
    const int i = blockIdx.x * 256 + threadIdx.x;
    if (i < 65536) {                       // [Wf;Wg]^T : n 0..127
        int n = i >> 9, k = i & 511;
        float v = (n < 64) ? Wf[k * DDIM + n] : Wg[k * DDIM + (n - 64)];
        g_wfgT[i] = __float2bfloat16(v);
    } else {                               // Wh^T
        int j = i - 65536;
        int n = j >> 9, k = j & 511;
        g_whT[j] = __float2bfloat16(Wh[k * CDIM + n]);
    }
}

// ---------------------------------------------------------------------------
// Generic bf16 GEMM mainloop: BM=128, BN=NTILES*8, BK=64, 256 thr, 2-deep.
// ---------------------------------------------------------------------------
#define PSTR 72

extern __shared__ __align__(16) unsigned char psm[];

template <int NTILES>
__device__ __forceinline__ void load_chunk(
    const __nv_bfloat16* A, const __nv_bfloat16* BT,
    size_t strA, size_t strB, int m0, int n0, int c, int buf, int t)
{
    constexpr int A_T = 128 * PSTR * 2;
    constexpr int BUF = A_T + NTILES * 8 * PSTR * 2;
    __nv_bfloat16* sA = (__nv_bfloat16*)(psm + buf * BUF);
    __nv_bfloat16* sB = (__nv_bfloat16*)(psm + buf * BUF + A_T);
    #pragma unroll
    for (int r = 0; r < 4; r++) {
        int idx = t + 256 * r;
        int row = idx >> 3, ck = idx & 7;
        cp16(&sA[row * PSTR + ck * 8],
             A + (size_t)(m0 + row) * strA + c * 64 + ck * 8);
    }
    #pragma unroll
    for (int r = 0; r < NTILES / 4; r++) {
        int idx = t + 256 * r;
        int row = idx >> 3, ck = idx & 7;
        cp16(&sB[row * PSTR + ck * 8],
             BT + (size_t)(n0 + row) * strB + c * 64 + ck * 8);
    }
    cp_commit();
}

template <int NCHUNK, int NTILES>
__device__ __forceinline__ void gemm_mainloop(
    const __nv_bfloat16* A, const __nv_bfloat16* BT,
    size_t strA, size_t strB,
    int m0, int n0, int t, int w, int gid, int tig, float (*o)[4])
{
    constexpr int A_T = 128 * PSTR * 2;
    constexpr int BUF = A_T + NTILES * 8 * PSTR * 2;

    #pragma unroll
    for (int nt = 0; nt < NTILES; nt++)
        #pragma unroll
        for (int j = 0; j < 4; j++) o[nt][j] = 0.f;

    load_chunk<NTILES>(A, BT, strA, strB, m0, n0, 0, 0, t);
    load_chunk<NTILES>(A, BT, strA, strB, m0, n0, 1, 1, t);

    for (int c = 0; c < NCHUNK; ++c) {
        if (c + 2 < NCHUNK) asm volatile("cp.async.wait_group 1;\n");
        else                asm volatile("cp.async.wait_group 0;\n");
        __syncthreads();
        const int buf = c & 1;
        const __nv_bfloat16* sA = (const __nv_bfloat16*)(psm + buf * BUF);
        const __nv_bfloat16* sB = (const __nv_bfloat16*)(psm + buf * BUF + A_T);

        u32 fa[4][4];
        const __nv_bfloat16* frow = &sA[(w * 16 + gid) * PSTR];
        #pragma unroll
        for (int ks = 0; ks < 4; ks++) {
            fa[ks][0] = *(const u32*)&frow[ks * 16 + 2 * tig];
            fa[ks][1] = *(const u32*)&frow[8 * PSTR + ks * 16 + 2 * tig];
            fa[ks][2] = *(const u32*)&frow[ks * 16 + 2 * tig + 8];
            fa[ks][3] = *(const u32*)&frow[8 * PSTR + ks * 16 + 2 * tig + 8];
        }
        #pragma unroll
        for (int nt = 0; nt < NTILES; nt++) {
            const __nv_bfloat16* brow = &sB[(nt * 8 + gid) * PSTR + 2 * tig];
            #pragma unroll
            for (int ks = 0; ks < 4; ks++) {
                u32 b0 = *(const u32*)&brow[ks * 16];
                u32 b1 = *(const u32*)&brow[ks * 16 + 8];
                mma16816(o[nt], fa[ks], b0, b1);
            }
        }
        __syncthreads();
        if (c + 2 < NCHUNK) load_chunk<NTILES>(A, BT, strA, strB, m0, n0, c + 2, buf, t);
        else                cp_commit();
    }
}

#define SMEM_N8   ((128 * PSTR * 2 + 64 * PSTR * 2) * 2)    // 55296
#define SMEM_N16  ((128 * PSTR * 2 + 128 * PSTR * 2) * 2)   // 73728

// ---------------------------------------------------------------------------
// proj_fg: f and g in one BN=128 GEMM against [Wf;Wg]^T
// ---------------------------------------------------------------------------
__global__ void __launch_bounds__(256)
proj_fg(const __nv_bfloat16* __restrict__ A,
        const float* __restrict__ bf, const float* __restrict__ bg)
{
    const int m0 = blockIdx.x * 128;
    const int t = threadIdx.x, w = t >> 5, lane = t & 31;
    const int gid = lane >> 2, tig = lane & 3;

    float o[16][4];
    gemm_mainloop<8, 16>(A, g_wfgT, CDIM, CDIM, m0, 0, t, w, gid, tig, o);

    const int r0 = m0 + w * 16 + gid;
    #pragma unroll
    for (int nt = 0; nt < 16; nt++) {
        const int cc = nt * 8 + 2 * tig;           // 0..127
        __nv_bfloat16* dst0;
        __nv_bfloat16* dst1;
        float b0, b1;
        if (nt < 8) {
            b0 = bf[cc]; b1 = bf[cc + 1];
            dst0 = &g_fb[(size_t)r0 * DDIM + cc];
            dst1 = &g_fb[(size_t)(r0 + 8) * DDIM + cc];
        } else {
            b0 = bg[cc - 64]; b1 = bg[cc - 63];
            dst0 = &g_gb[(size_t)r0 * DDIM + cc - 64];
            dst1 = &g_gb[(size_t)(r0 + 8) * DDIM + cc - 64];
        }
        __nv_bfloat162 v0 = __floats2bfloat162_rn(o[nt][0] + b0, o[nt][1] + b1);
        __nv_bfloat162 v1 = __floats2bfloat162_rn(o[nt][2] + b0, o[nt][3] + b1);
        *(__nv_bfloat162*)dst0 = v0;
        *(__nv_bfloat162*)dst1 = v1;
    }
}

// ---------------------------------------------------------------------------
// proj_big: h projection, BN=64, transposed bf16 store
// ---------------------------------------------------------------------------
#define TSTR 136
__global__ void __launch_bounds__(256)
proj_big(const __nv_bfloat16* __restrict__ A, const float* __restrict__ bias)
{
    const int m0 = blockIdx.x * 128;
    const int n0 = blockIdx.y * 64;
    const int t = threadIdx.x, w = t >> 5, lane = t & 31;
    const int gid = lane >> 2, tig = lane & 3;

    float o[8][4];
    gemm_mainloop<8, 8>(A, g_whT, CDIM, CDIM, m0, n0, t, w, gid, tig, o);

    __nv_bfloat16* st = (__nv_bfloat16*)psm;
    __syncthreads();
    const int m = w * 16 + gid;
    #pragma unroll
    for (int nt = 0; nt < 8; nt++) {
        const int cc = nt * 8 + 2 * tig;
        const float b0 = bias[n0 + cc], b1 = bias[n0 + cc + 1];
        st[cc * TSTR + m]           = __float2bfloat16(o[nt][0] + b0);
        st[(cc + 1) * TSTR + m]     = __float2bfloat16(o[nt][1] + b1);
        st[cc * TSTR + m + 8]       = __float2bfloat16(o[nt][2] + b0);
        st[(cc + 1) * TSTR + m + 8] = __float2bfloat16(o[nt][3] + b1);
    }
    __syncthreads();

    const int b  = m0 >> 12;
    const int nb = m0 & 4095;
    #pragma unroll
    for (int r = 0; r < 4; r++) {
        int idx = t + 256 * r;
        int row = idx >> 4, seg = idx & 15;
        float4 v = *(const float4*)&st[row * TSTR + seg * 8];
        *(float4*)&g_hTb[((size_t)b * CDIM + n0 + row) * SEQ + nb + seg * 8] = v;
    }
}

// ---------------------------------------------------------------------------
// skernel: P[q][k] = exp(f_q . g_k) + partial row sums, staged stores
// (round-10 proven, 399.5 config)
// ---------------------------------------------------------------------------
#define PTS 136

__global__ void __launch_bounds__(256)
skernel()
{
    __shared__ __align__(16) __nv_bfloat16 sbuf[2 * 128 * PSTR];  // 36864 B

    __nv_bfloat16* sf = sbuf;
    __nv_bfloat16* sg = sbuf + 128 * PSTR;

    const int qb = blockIdx.x, kb = blockIdx.y, b = blockIdx.z;
    const int q0 = qb * 128, k0 = kb * 128;
    const int t = threadIdx.x, w = t >> 5, lane = t & 31;
    const int gid = lane >> 2, tig = lane & 3;

    const __nv_bfloat16* fptr = g_fb + (size_t)(b * SEQ + q0) * DDIM;
    const __nv_bfloat16* gptr = g_gb + (size_t)(b * SEQ + k0) * DDIM;
    #pragma unroll
    for (int r = 0; r < 4; r++) {
        int idx = t + 256 * r;
        int row = idx >> 3, ck = idx & 7;
        cp16(&sf[row * PSTR + ck * 8], fptr + (size_t)row * DDIM + ck * 8);
    }
    #pragma unroll
    for (int r = 0; r < 4; r++) {
        int idx = t + 256 * r;
        int row = idx >> 3, ck = idx & 7;
        cp16(&sg[row * PSTR + ck * 8], gptr + (size_t)row * DDIM + ck * 8);
    }
    cp_commit();
    asm volatile("cp.async.wait_group 0;\n");
    __syncthreads();

    u32 fa[4][4];
    {
        const __nv_bfloat16* frow = &sf[(w * 16 + gid) * PSTR];
        #pragma unroll
        for (int ks = 0; ks < 4; ks++) {
            fa[ks][0] = *(const u32*)&frow[ks * 16 + 2 * tig];
            fa[ks][1] = *(const u32*)&frow[8 * PSTR + ks * 16 + 2 * tig];
            fa[ks][2] = *(const u32*)&frow[ks * 16 + 2 * tig + 8];
            fa[ks][3] = *(const u32*)&frow[8 * PSTR + ks * 16 + 2 * tig + 8];
        }
    }

    float s[16][4];
    #pragma unroll
    for (int nt = 0; nt < 16; nt++)
        #pragma unroll
        for (int j = 0; j < 4; j++) s[nt][j] = 0.f;

    #pragma unroll
    for (int nt = 0; nt < 16; nt++) {
        const __nv_bfloat16* brow = &sg[(nt * 8 + gid) * PSTR + 2 * tig];
        #pragma unroll
        for (int ks = 0; ks < 4; ks++) {
            u32 b0 = *(const u32*)&brow[ks * 16];
            u32 b1 = *(const u32*)&brow[ks * 16 + 8];
            mma16816(s[nt], fa[ks], b0, b1);
        }
    }
    __syncthreads();   // sf/sg reads done; sbuf becomes the P staging tile

    __nv_bfloat16* sp = sbuf;
    const int rl0 = w * 16 + gid;
    const int rl1 = rl0 + 8;
    float sl0 = 0.f, sl1 = 0.f;
    #pragma unroll
    for (int nt = 0; nt < 16; nt++) {
        float p0 = __expf(s[nt][0]);
        float p1 = __expf(s[nt][1]);
        float p2 = __expf(s[nt][2]);
        float p3 = __expf(s[nt][3]);
        sl0 += p0 + p1;
        sl1 += p2 + p3;
        const int key = nt * 8 + 2 * tig;
        __nv_bfloat162 lo = __floats2bfloat162_rn(p0, p1);
        __nv_bfloat162 hi = __floats2bfloat162_rn(p2, p3);
        *(__nv_bfloat162*)&sp[rl0 * PTS + key] = lo;
        *(__nv_bfloat162*)&sp[rl1 * PTS + key] = hi;
    }
    sl0 += __shfl_xor_sync(0xffffffffu, sl0, 1);
    sl0 += __shfl_xor_sync(0xffffffffu, sl0, 2);
    sl1 += __shfl_xor_sync(0xffffffffu, sl1, 1);
    sl1 += __shfl_xor_sync(0xffffffffu, sl1, 2);
    if (tig == 0) {
        g_lpart[kb * MROWS + b * SEQ + q0 + rl0] = sl0;
        g_lpart[kb * MROWS + b * SEQ + q0 + rl1] = sl1;
    }
    __syncthreads();

    // coalesced 16B stores: 128 rows x 16 float4
    __nv_bfloat16* P = g_pb + (size_t)b * SEQ * SEQ;
    #pragma unroll
    for (int r = 0; r < 8; r++) {
        int idx = t + 256 * r;
        int row = idx >> 4, seg = idx & 15;
        float4 v = *(const float4*)&sp[row * PTS + seg * 8];
        *(float4*)&P[(size_t)(q0 + row) * SEQ + k0 + seg * 8] = v;
    }
}

__global__ void __launch_bounds__(256)
reduce_l()
{
    const int m = blockIdx.x * 256 + threadIdx.x;
    float s = 0.f;
    #pragma unroll
    for (int kb = 0; kb < NKB; kb++) s += g_lpart[kb * MROWS + m];
    g_l[m] = s;
}

// ---------------------------------------------------------------------------
// pvkernel: out = x + (gamma/l[row]) * (P . h^T). BM=128, BN=128, BK=64.
// 3-stage pipeline, ONE __syncthreads per chunk, 2 CTAs/SM guaranteed.
// ---------------------------------------------------------------------------
#define PV_A_T  (128 * PSTR * 2)            // 18432
#define PV_BUF  (2 * PV_A_T)                // 36864 (A + B tiles)
#define SMEM_PV (3 * PV_BUF)                // 110592

__device__ __forceinline__ void pv_load_chunk(
    const __nv_bfloat16* Pq, const __nv_bfloat16* BT, int n0, int c, int buf, int t)
{
    __nv_bfloat16* sA = (__nv_bfloat16*)(psm + buf * PV_BUF);
    __nv_bfloat16* sB = (__nv_bfloat16*)(psm + buf * PV_BUF + PV_A_T);
    #pragma unroll
    for (int r = 0; r < 4; r++) {
        int idx = t + 256 * r;
        int row = idx >> 3, ck = idx & 7;
        cp16(&sA[row * PSTR + ck * 8],
             Pq + (size_t)row * SEQ + c * 64 + ck * 8);
    }
    #pragma unroll
    for (int r = 0; r < 4; r++) {
        int idx = t + 256 * r;
        int row = idx >> 3, ck = idx & 7;
        cp16(&sB[row * PSTR + ck * 8],
             BT + (size_t)(n0 + row) * SEQ + c * 64 + ck * 8);
    }
    cp_commit();
}

__global__ void __launch_bounds__(256, 2)
pvkernel(const float* __restrict__ x, const float* __restrict__ gamma_p,
         float* __restrict__ out)
{
    const int n0 = blockIdx.x * 128;    // channel block (x-major for P L2 reuse)
    const int m0 = blockIdx.y * 128;    // global row block
    const int b  = m0 >> 12;
    const int t = threadIdx.x, w = t >> 5, lane = t & 31;
    const int gid = lane >> 2, tig = lane & 3;

    const __nv_bfloat16* Pq = g_pb + ((size_t)b * SEQ + (m0 & 4095)) * SEQ;
    const __nv_bfloat16* BT = g_hTb + (size_t)b * CDIM * SEQ;

    float o[16][4];
    #pragma unroll
    for (int nt = 0; nt < 16; nt++)
        #pragma unroll
        for (int j = 0; j < 4; j++) o[nt][j] = 0.f;

    pv_load_chunk(Pq, BT, n0, 0, 0, t);
    pv_load_chunk(Pq, BT, n0, 1, 1, t);

    const int NCH = SEQ / 64;           // 64
    for (int c = 0; c < NCH; ++c) {
        if (c + 1 < NCH) asm volatile("cp.async.wait_group 1;\n");
        else             asm volatile("cp.async.wait_group 0;\n");
        __syncthreads();   // stage c visible; all warps done with stage c-1

        // prefetch stage c+2 into buf (c+2)%3 (that buffer was consumed at c-1)
        if (c + 2 < NCH) pv_load_chunk(Pq, BT, n0, c + 2, (c + 2) % 3, t);

        const int buf = c % 3;
        const __nv_bfloat16* sA = (const __nv_bfloat16*)(psm + buf * PV_BUF);
        const __nv_bfloat16* sB = (const __nv_bfloat16*)(psm + buf * PV_BUF + PV_A_T);

        u32 fa[4][4];
        const __nv_bfloat16* frow = &sA[(w * 16 + gid) * PSTR];
        #pragma unroll
        for (int ks = 0; ks < 4; ks++) {
            fa[ks][0] = *(const u32*)&frow[ks * 16 + 2 * tig];
            fa[ks][1] = *(const u32*)&frow[8 * PSTR + ks * 16 + 2 * tig];
            fa[ks][2] = *(const u32*)&frow[ks * 16 + 2 * tig + 8];
            fa[ks][3] = *(const u32*)&frow[8 * PSTR + ks * 16 + 2 * tig + 8];
        }
        #pragma unroll
        for (int nt = 0; nt < 16; nt++) {
            const __nv_bfloat16* brow = &sB[(nt * 8 + gid) * PSTR + 2 * tig];
            #pragma unroll
            for (int ks = 0; ks < 4; ks++) {
                u32 b0 = *(const u32*)&brow[ks * 16];
                u32 b1 = *(const u32*)&brow[ks * 16 + 8];
                mma16816(o[nt], fa[ks], b0, b1);
            }
        }
    }

    const float gamma = *gamma_p;
    const int r0 = m0 + w * 16 + gid;
    const int r1 = r0 + 8;
    const float sc0 = gamma / g_l[r0];
    const float sc1 = gamma / g_l[r1];
    #pragma unroll
    for (int nt = 0; nt < 16; nt++) {
        const int cc = n0 + nt * 8 + 2 * tig;
        float2 x0 = *(const float2*)&x[(size_t)r0 * CDIM + cc];
        float2 x1 = *(const float2*)&x[(size_t)r1 * CDIM + cc];
        float2 o0, o1;
        o0.x = fmaf(o[nt][0], sc0, x0.x);
        o0.y = fmaf(o[nt][1], sc0, x0.y);
        o1.x = fmaf(o[nt][2], sc1, x1.x);
        o1.y = fmaf(o[nt][3], sc1, x1.y);
        *(float2*)&out[(size_t)r0 * CDIM + cc] = o0;
        *(float2*)&out[(size_t)r1 * CDIM + cc] = o1;
    }
}

// ---------------------------------------------------------------------------
extern "C" void kernel_launch(void* const* d_in, const int* in_sizes, int n_in,
                              void* d_out, int out_size)
{
    const float* x     = (const float*)d_in[0];
    const float* Wf    = (const float*)d_in[1];
    const float* bf    = (const float*)d_in[2];
    const float* Wg    = (const float*)d_in[3];
    const float* bg    = (const float*)d_in[4];
    const float* Wh    = (const float*)d_in[5];
    const float* bh    = (const float*)d_in[6];
    const float* gamma = (const float*)d_in[7];
    float* out = (float*)d_out;

    __nv_bfloat16* xb;
    cudaGetSymbolAddress((void**)&xb, g_xb);

    static cudaStream_t s1 = nullptr;
    static cudaEvent_t  e0 = nullptr, e1 = nullptr;
    if (!s1) {
        cudaStreamCreateWithFlags(&s1, cudaStreamNonBlocking);
        cudaEventCreateWithFlags(&e0, cudaEventDisableTiming);
        cudaEventCreateWithFlags(&e1, cudaEventDisableTiming);
        cudaFuncSetAttribute(proj_fg,
                             cudaFuncAttributeMaxDynamicSharedMemorySize, SMEM_N16);
        cudaFuncSetAttribute(proj_big,
                             cudaFuncAttributeMaxDynamicSharedMemorySize, SMEM_N8);
        cudaFuncSetAttribute(pvkernel,
                             cudaFuncAttributeMaxDynamicSharedMemorySize, SMEM_PV);
    }

    // default stream: casts, then fork
    cast_x <<<MROWS * CDIM / 4 / 256, 256>>>(x, xb);
    cast_w3<<<(65536 + CDIM * CDIM) / 256, 256>>>(Wf, Wg, Wh);
    cudaEventRecord(e0, 0);

    // side stream: f+g projection -> S/P/exp -> l reduction
    cudaStreamWaitEvent(s1, e0, 0);
    proj_fg <<<dim3(MROWS / 128), 256, SMEM_N16, s1>>>(xb, bf, bg);
    skernel <<<dim3(SEQ / 128, SEQ / 128, BATCH), 256, 0, s1>>>();
    reduce_l<<<MROWS / 256, 256, 0, s1>>>();
    cudaEventRecord(e1, s1);

    // default stream: h projection overlaps the side stream
    proj_big<<<dim3(MROWS / 128, CDIM / 64), 256, SMEM_N8>>>(xb, bh);

    // join, then PV
    cudaStreamWaitEvent(0, e1, 0);
    pvkernel<<<dim3(CDIM / 128, MROWS / 128), 256, SMEM_PV>>>(x, gamma, out);
}